// round 13
// baseline (speedup 1.0000x reference)
#include <cuda_runtime.h>
#include <math.h>

#define B_  64
#define N_  2048
#define K_  128
#define J_  10
#define D_  16
#define F_  160   // J_*D_

typedef unsigned long long u64;

// scratch (device globals: no allocation allowed)
__device__ float g_s8[B_*8*K_];        // per-chunk partial sums of u
__device__ float g_v [B_*J_*K_];       // v[b,j,k]
__device__ float g_ps[512*J_*K_];      // per-block partial p slices
__device__ unsigned g_cnt_sum[B_];     // election counters (mod-8, never reset)
__device__ unsigned g_cnt_pass[2][B_];

__device__ __forceinline__ u64 ffma2(u64 a, u64 b, u64 c) {
    u64 d; asm("fma.rn.f32x2 %0, %1, %2, %3;" : "=l"(d) : "l"(a), "l"(b), "l"(c));
    return d;
}
__device__ __forceinline__ u64 pack2(float x, float y) {
    u64 d; asm("mov.b64 %0, {%1, %2};" : "=l"(d) : "f"(x), "f"(y));
    return d;
}
__device__ __forceinline__ float2 unpack2(u64 v) {
    float2 r; asm("mov.b64 {%0, %1}, %2;" : "=f"(r.x), "=f"(r.y) : "l"(v));
    return r;
}

// launch 1: partial sums of u + (tail, per-b elected block) o0 & v1
__global__ void k_sum(const float* __restrict__ u, const float* __restrict__ W) {
    int b = blockIdx.y, chunk = blockIdx.x;   // 8 chunks x 64 b
    int tid = threadIdx.x;
    int k4 = tid & 31, rg = tid >> 5;
    const float4* up = (const float4*)(u + ((size_t)b*N_ + chunk*256 + rg*32)*K_);
    float4 acc = make_float4(0.f,0.f,0.f,0.f);
#pragma unroll 8
    for (int r = 0; r < 32; r++) {
        float4 t = up[r*32 + k4];
        acc.x += t.x; acc.y += t.y; acc.z += t.z; acc.w += t.w;
    }
    __shared__ float4 sred[8][32];
    sred[rg][k4] = acc;
    __syncthreads();
    if (rg == 0) {
#pragma unroll
        for (int i = 1; i < 8; i++) {
            float4 t = sred[i][k4];
            acc.x += t.x; acc.y += t.y; acc.z += t.z; acc.w += t.w;
        }
        ((float4*)(g_s8 + (b*8 + chunk)*K_))[k4] = acc;   // plain store, no atomics
    }
    // ---- election: last of the 8 chunks for this b runs the ov0 tail ----
    __threadfence();
    __syncthreads();
    __shared__ int last;
    if (tid == 0) last = ((atomicAdd(&g_cnt_sum[b], 1u) & 7u) == 7u);
    __syncthreads();
    if (!last) return;
    __threadfence();

    __shared__ float ss[K_];
    __shared__ float so[F_];
    if (tid < K_) {
        float a = 0.f;
#pragma unroll
        for (int c = 0; c < 8; c++) a += g_s8[(b*8 + c)*K_ + tid];
        ss[tid] = a;
    }
    __syncthreads();
    if (tid < F_) {           // o0[f] = 0.1 * sum_k s[k] * W[k,f]
        float a = 0.f;
#pragma unroll 8
        for (int k = 0; k < K_; k++) a += ss[k] * W[k*F_ + tid];
        so[tid] = 0.1f * a;
    }
    __syncthreads();
    for (int e = tid; e < J_*K_; e += 256) {   // v1[j,k] = sum_d o[j,d] W[k,jd]
        int jj = e >> 7, k = e & 127;
        const float* wr = W + k*F_ + jj*D_;
        const float* oj = so + jj*D_;
        float v = 0.f;
#pragma unroll
        for (int d2 = 0; d2 < D_; d2++) v += oj[d2] * wr[d2];
        g_v[b*J_*K_ + e] = v;
    }
}

// launches 2+3: fused routing pass (8 rows/warp-iter, oct-relative loads),
// block partial written as plain slice; elected per-b block runs the tail:
//   which==0 -> o1 & v2 (overwrites g_v[b], safe: all readers of b done)
//   which==1 -> o2 -> squash -> out
__global__ void __launch_bounds__(256, 2)
k_pass(const float* __restrict__ u, const float* __restrict__ W,
       float* __restrict__ out, int which) {
    int b = blockIdx.x >> 3;
    int seg = blockIdx.x & 7;              // 256 rows per block
    int tid = threadIdx.x;
    int warp = tid >> 5, lane = tid & 31;
    int oct = lane >> 2;

    __shared__ float sv[J_*K_];
    __shared__ float ps[J_*K_];
    {
        const float* vb = g_v + b*J_*K_;
        for (int i = tid; i < J_*K_; i += 256) { sv[i] = vb[i]; ps[i] = 0.f; }
    }
    __syncthreads();

    u64 p20[J_], p21[J_];
#pragma unroll
    for (int j = 0; j < J_; j++) { p20[j] = 0ULL; p21[j] = 0ULL; }

    const float4* ub = (const float4*)(u + ((size_t)b*N_ + (size_t)seg*256)*K_);
    const float4* svl = ((const float4*)sv) + lane;   // sv[j*K_ + 4*lane]

#pragma unroll 1
    for (int it = 0; it < 4; it++) {
        int r0 = warp*32 + it*8;
        u64 a0[8], a1[8];
#pragma unroll
        for (int r = 0; r < 8; r++) {
            float4 t = ub[(r0 + (oct ^ r))*32 + lane];
            a0[r] = pack2(t.x, t.y);
            a1[r] = pack2(t.z, t.w);
        }

        float pd[J_];
#pragma unroll
        for (int j = 0; j < J_; j++) {
            float4 vv = svl[j*32];         // conflict-free LDS.128
            u64 v0 = pack2(vv.x, vv.y);
            u64 v1 = pack2(vv.z, vv.w);
            float s[8];
#pragma unroll
            for (int r = 0; r < 8; r++) {
                u64 acc = ffma2(a0[r], v0, ffma2(a1[r], v1, 0ULL));
                float2 f = unpack2(acc);
                s[r] = f.x + f.y;
            }
            s[0] += __shfl_xor_sync(0xffffffffu, s[4], 16);
            s[1] += __shfl_xor_sync(0xffffffffu, s[5], 16);
            s[2] += __shfl_xor_sync(0xffffffffu, s[6], 16);
            s[3] += __shfl_xor_sync(0xffffffffu, s[7], 16);
            s[0] += __shfl_xor_sync(0xffffffffu, s[2], 8);
            s[1] += __shfl_xor_sync(0xffffffffu, s[3], 8);
            s[0] += __shfl_xor_sync(0xffffffffu, s[1], 4);
            s[0] += __shfl_xor_sync(0xffffffffu, s[0], 2);
            s[0] += __shfl_xor_sync(0xffffffffu, s[0], 1);
            pd[j] = s[0];                   // full dot of row r0+oct
        }
        float m01 = fmaxf(pd[0], pd[1]), m23 = fmaxf(pd[2], pd[3]);
        float m45 = fmaxf(pd[4], pd[5]), m67 = fmaxf(pd[6], pd[7]);
        float m89 = fmaxf(pd[8], pd[9]);
        float mx = fmaxf(fmaxf(fmaxf(m01, m23), fmaxf(m45, m67)), m89);
        float Z = 0.f;
#pragma unroll
        for (int j = 0; j < J_; j++) { pd[j] = __expf(pd[j] - mx); Z += pd[j]; }
        float rZ = __fdividef(1.0f, Z);
#pragma unroll
        for (int j = 0; j < J_; j++) {
            float c0 = pd[j] * rZ;          // row r0+oct
            u64 cc = pack2(c0, c0);
            p20[j] = ffma2(cc, a0[0], p20[j]);
            p21[j] = ffma2(cc, a1[0], p21[j]);
#pragma unroll
            for (int r = 1; r < 8; r++) {
                float cr = __shfl_xor_sync(0xffffffffu, c0, r << 2);
                cc = pack2(cr, cr);
                p20[j] = ffma2(cc, a0[r], p20[j]);
                p21[j] = ffma2(cc, a1[r], p21[j]);
            }
        }
    }

    // aggregate the 8 warps via smem, then write this block's slice (plain STG)
#pragma unroll
    for (int j = 0; j < J_; j++) {
        float2 a = unpack2(p20[j]);
        float2 c = unpack2(p21[j]);
        float* d = ps + j*K_ + lane*4;
        atomicAdd(d+0, a.x); atomicAdd(d+1, a.y);
        atomicAdd(d+2, c.x); atomicAdd(d+3, c.y);
    }
    __syncthreads();
    {
        float* dst = g_ps + (size_t)blockIdx.x*J_*K_;
        for (int i = tid; i < J_*K_; i += 256) dst[i] = ps[i];
    }

    // ---- election: last of the 8 blocks for this b runs the tail ----
    __threadfence();
    __syncthreads();
    __shared__ int last;
    if (tid == 0) last = ((atomicAdd(&g_cnt_pass[which][b], 1u) & 7u) == 7u);
    __syncthreads();
    if (!last) return;
    __threadfence();

    // sum the 8 slices for b into ps (fixed order -> deterministic)
    for (int i = tid; i < J_*K_; i += 256) {
        float a = 0.f;
#pragma unroll
        for (int c = 0; c < 8; c++) a += g_ps[(size_t)((b<<3) + c)*J_*K_ + i];
        ps[i] = a;
    }
    __syncthreads();

    // o[f] = sum_k p[j(f),k] * W[k,f]   (reuse sv[0..159] as o buffer)
    if (tid < F_) {
        int j = tid >> 4;
        float a = 0.f;
#pragma unroll 8
        for (int k = 0; k < K_; k++) a += ps[j*K_ + k] * W[k*F_ + tid];
        sv[tid] = a;
    }
    __syncthreads();

    if (which == 0) {
        // v2[j,k] = sum_d o[j,d] * W[k,jd]  -> overwrite g_v[b]
        for (int e = tid; e < J_*K_; e += 256) {
            int jj = e >> 7, k = e & 127;
            const float* wr = W + k*F_ + jj*D_;
            const float* oj = sv + jj*D_;
            float v = 0.f;
#pragma unroll
            for (int d2 = 0; d2 < D_; d2++) v += oj[d2] * wr[d2];
            g_v[b*J_*K_ + e] = v;
        }
    } else {
        // squash(o2) -> out
        if (tid < F_) {
            int j = tid >> 4;
            float s2 = 0.f;
#pragma unroll
            for (int d2 = 0; d2 < D_; d2++) { float x = sv[j*D_ + d2]; s2 += x*x; }
            out[b*F_ + tid] = sv[tid] * s2 / ((1.f + s2) * sqrtf(s2 + 1e-7f));
        }
    }
}

extern "C" void kernel_launch(void* const* d_in, const int* in_sizes, int n_in,
                              void* d_out, int out_size) {
    const float* u = (const float*)d_in[0];
    const float* W = (const float*)d_in[1];
    float* out = (float*)d_out;

    k_sum<<<dim3(8, B_), 256>>>(u, W);       // partial sums + o0/v1 tail
    k_pass<<<512, 256>>>(u, W, out, 0);      // pass 1 + o1/v2 tail
    k_pass<<<512, 256>>>(u, W, out, 1);      // pass 2 + squash tail
}

// round 15
// speedup vs baseline: 1.6162x; 1.6162x over previous
#include <cuda_runtime.h>
#include <math.h>

#define B_  64
#define N_  2048
#define K_  128
#define J_  10
#define D_  16
#define F_  160   // J_*D_

typedef unsigned long long u64;

// scratch (device globals: no allocation allowed)
__device__ float g_s8[B_*8*K_];      // per-chunk partial sums of u
__device__ float g_wt[F_*K_];        // W transposed: wt[f*128 + k] = W[k*160 + f]
__device__ float g_v [B_*J_*K_];     // v[b,j,k]
__device__ float g_p1[B_*J_*K_];     // p after routing iter 1
__device__ float g_p2[B_*J_*K_];     // p after routing iter 2

__device__ __forceinline__ u64 ffma2(u64 a, u64 b, u64 c) {
    u64 d; asm("fma.rn.f32x2 %0, %1, %2, %3;" : "=l"(d) : "l"(a), "l"(b), "l"(c));
    return d;
}
__device__ __forceinline__ u64 pack2(float x, float y) {
    u64 d; asm("mov.b64 %0, {%1, %2};" : "=l"(d) : "f"(x), "f"(y));
    return d;
}
__device__ __forceinline__ float2 unpack2(u64 v) {
    float2 r; asm("mov.b64 {%0, %1}, %2;" : "=f"(r.x), "=f"(r.y) : "l"(v));
    return r;
}

// launch 1: per-chunk partial sums of u (plain stores, no atomics) +
// spread housekeeping (zero p1/p2, transpose W) over the 512 blocks.
// NOTE: housekeeping uses strided loops over the REAL 256 threads (R14 bug fix).
__global__ void k_sum(const float* __restrict__ u, const float* __restrict__ W) {
    int b = blockIdx.y, chunk = blockIdx.x;   // 8 chunks x 64 b
    int tid = threadIdx.x;
    int gid = b*8 + chunk;                    // 0..511
    // housekeeping: 320 p-zeros + 40 transposes per block (360 items, 256 threads)
    for (int i = tid; i < 360; i += 256) {
        if (i < 320) {
            int i0 = gid*320 + i;             // 512*320 = 163840 = 2*81920
            if (i0 < B_*J_*K_) g_p1[i0] = 0.f;
            else               g_p2[i0 - B_*J_*K_] = 0.f;
        } else {
            int w0 = gid*40 + (i - 320);      // 512*40 = 20480 = F_*K_
            int f = w0 >> 7, k = w0 & 127;
            g_wt[w0] = W[k*F_ + f];
        }
    }
    int k4 = tid & 31, rg = tid >> 5;
    const float4* up = (const float4*)(u + ((size_t)b*N_ + chunk*256 + rg*32)*K_);
    float4 acc = make_float4(0.f,0.f,0.f,0.f);
#pragma unroll 8
    for (int r = 0; r < 32; r++) {
        float4 t = up[r*32 + k4];
        acc.x += t.x; acc.y += t.y; acc.z += t.z; acc.w += t.w;
    }
    __shared__ float4 sred[8][32];
    sred[rg][k4] = acc;
    __syncthreads();
    if (rg == 0) {
#pragma unroll
        for (int i = 1; i < 8; i++) {
            float4 t = sred[i][k4];
            acc.x += t.x; acc.y += t.y; acc.z += t.z; acc.w += t.w;
        }
        ((float4*)(g_s8 + (b*8 + chunk)*K_))[k4] = acc;
    }
}

// mode 0: o[b,j,d] = 0.1 * sum_k s[b,k]   * W[k, j*16+d]  (s from g_s8 slices)
// mode 1: o[b,j,d] =       sum_k p1[b,j,k]* W[k, j*16+d]
// then    v[b,j,k] = sum_d o[b,j,d] * W[k, j*16+d]
// Phase A: warp-per-f with coalesced g_wt loads + 5-shfl butterfly (proven fast).
__global__ void k_ov(const float* __restrict__ W, int mode) {
    int b = blockIdx.x, t = threadIdx.x;   // 256 threads, 8 warps
    int warp = t >> 5, lane = t & 31;
    __shared__ float src[J_*K_];
    __shared__ float so[F_];
    if (mode == 0) {
        if (t < K_) {
            float a = 0.f;
#pragma unroll
            for (int c = 0; c < 8; c++) a += g_s8[(b*8 + c)*K_ + t];
            src[t] = a;
        }
    } else {
        for (int i = t; i < J_*K_; i += 256) src[i] = g_p1[b*J_*K_ + i];
    }
    __syncthreads();

    // phase A: warp w computes f = w, w+8, ..., w+152
#pragma unroll
    for (int fi = 0; fi < 20; fi++) {
        int f = warp + fi*8;
        float4 w4 = ((const float4*)(g_wt + f*K_))[lane];
        const float* sp = (mode == 0) ? src : (src + (f >> 4)*K_);
        float4 s4 = ((const float4*)sp)[lane];
        u64 acc = ffma2(pack2(w4.x, w4.y), pack2(s4.x, s4.y),
                  ffma2(pack2(w4.z, w4.w), pack2(s4.z, s4.w), 0ULL));
        float2 fr = unpack2(acc);
        float d = fr.x + fr.y;
#pragma unroll
        for (int m = 16; m >= 1; m >>= 1)
            d += __shfl_xor_sync(0xffffffffu, d, m);
        if (lane == 0) so[f] = (mode == 0) ? 0.1f * d : d;
    }
    __syncthreads();

    // phase B: v[j,k] = sum_d o[j,d] * W[k, j*16+d]
#pragma unroll
    for (int e = t; e < J_*K_; e += 256) {
        int jj = e >> 7, k = e & 127;
        const float4* wrow = (const float4*)(W + k*F_ + jj*D_);
        const float4* oj = (const float4*)(so + jj*D_);
        float4 w0 = wrow[0], w1 = wrow[1], w2 = wrow[2], w3 = wrow[3];
        float4 o0 = oj[0], o1 = oj[1], o2 = oj[2], o3 = oj[3];
        float v = w0.x*o0.x + w0.y*o0.y + w0.z*o0.z + w0.w*o0.w
                + w1.x*o1.x + w1.y*o1.y + w1.z*o1.z + w1.w*o1.w
                + w2.x*o2.x + w2.y*o2.y + w2.z*o2.z + w2.w*o2.w
                + w3.x*o3.x + w3.y*o3.y + w3.z*o3.z + w3.w*o3.w;
        g_v[b*J_*K_ + e] = v;
    }
}

// fused pass: dots -> softmax -> p accumulation, 8 rows per warp-iteration.
// 512 rows per block (grid 256 = single wave at occ-2): halves per-block
// fixed costs vs R12. Inner loop identical to R12 (37.3us proven).
__global__ void __launch_bounds__(256, 2)
k_pass(const float* __restrict__ u, int which) {
    float* p = (which == 0) ? g_p1 : g_p2;
    int b = blockIdx.x >> 2;
    int seg = blockIdx.x & 3;              // 512 rows per block
    int tid = threadIdx.x;
    int warp = tid >> 5, lane = tid & 31;
    int oct = lane >> 2;

    __shared__ float sv[J_*K_];
    __shared__ float ps[J_*K_];
    {
        const float* vb = g_v + b*J_*K_;
        for (int i = tid; i < J_*K_; i += 256) { sv[i] = vb[i]; ps[i] = 0.f; }
    }
    __syncthreads();

    u64 p20[J_], p21[J_];
#pragma unroll
    for (int j = 0; j < J_; j++) { p20[j] = 0ULL; p21[j] = 0ULL; }

    const float4* ub = (const float4*)(u + ((size_t)b*N_ + (size_t)seg*512)*K_);
    const float4* svl = ((const float4*)sv) + lane;   // sv[j*K_ + 4*lane]

#pragma unroll 1
    for (int it = 0; it < 8; it++) {
        int r0 = warp*64 + it*8;
        u64 a0[8], a1[8];
#pragma unroll
        for (int r = 0; r < 8; r++) {
            float4 t = ub[(r0 + (oct ^ r))*32 + lane];
            a0[r] = pack2(t.x, t.y);
            a1[r] = pack2(t.z, t.w);
        }

        float pd[J_];
#pragma unroll
        for (int j = 0; j < J_; j++) {
            float4 vv = svl[j*32];         // conflict-free LDS.128
            u64 v0 = pack2(vv.x, vv.y);
            u64 v1 = pack2(vv.z, vv.w);
            float s[8];
#pragma unroll
            for (int r = 0; r < 8; r++) {
                u64 acc = ffma2(a0[r], v0, ffma2(a1[r], v1, 0ULL));
                float2 f = unpack2(acc);
                s[r] = f.x + f.y;
            }
            s[0] += __shfl_xor_sync(0xffffffffu, s[4], 16);
            s[1] += __shfl_xor_sync(0xffffffffu, s[5], 16);
            s[2] += __shfl_xor_sync(0xffffffffu, s[6], 16);
            s[3] += __shfl_xor_sync(0xffffffffu, s[7], 16);
            s[0] += __shfl_xor_sync(0xffffffffu, s[2], 8);
            s[1] += __shfl_xor_sync(0xffffffffu, s[3], 8);
            s[0] += __shfl_xor_sync(0xffffffffu, s[1], 4);
            s[0] += __shfl_xor_sync(0xffffffffu, s[0], 2);
            s[0] += __shfl_xor_sync(0xffffffffu, s[0], 1);
            pd[j] = s[0];                   // full dot of row r0+oct
        }
        float m01 = fmaxf(pd[0], pd[1]), m23 = fmaxf(pd[2], pd[3]);
        float m45 = fmaxf(pd[4], pd[5]), m67 = fmaxf(pd[6], pd[7]);
        float m89 = fmaxf(pd[8], pd[9]);
        float mx = fmaxf(fmaxf(fmaxf(m01, m23), fmaxf(m45, m67)), m89);
        float Z = 0.f;
#pragma unroll
        for (int j = 0; j < J_; j++) { pd[j] = __expf(pd[j] - mx); Z += pd[j]; }
        float rZ = __fdividef(1.0f, Z);
#pragma unroll
        for (int j = 0; j < J_; j++) {
            float c0 = pd[j] * rZ;          // row r0+oct
            u64 cc = pack2(c0, c0);
            p20[j] = ffma2(cc, a0[0], p20[j]);
            p21[j] = ffma2(cc, a1[0], p21[j]);
#pragma unroll
            for (int r = 1; r < 8; r++) {
                float cr = __shfl_xor_sync(0xffffffffu, c0, r << 2);
                cc = pack2(cr, cr);
                p20[j] = ffma2(cc, a0[r], p20[j]);
                p21[j] = ffma2(cc, a1[r], p21[j]);
            }
        }
    }

    // aggregate the 8 warps via smem, then 1 coalesced gmem atomic pass
#pragma unroll
    for (int j = 0; j < J_; j++) {
        float2 a = unpack2(p20[j]);
        float2 c = unpack2(p21[j]);
        float* d = ps + j*K_ + lane*4;
        atomicAdd(d+0, a.x); atomicAdd(d+1, a.y);
        atomicAdd(d+2, c.x); atomicAdd(d+3, c.y);
    }
    __syncthreads();
    float* pb = p + b*J_*K_;
    for (int i = tid; i < J_*K_; i += 256)
        atomicAdd(pb + i, ps[i]);
}

// o2[b,j,d] = sum_k p2[b,j,k]*W[k,jd]; out = squash(o2) over d
__global__ void k_final(const float* __restrict__ W, float* __restrict__ out) {
    int b = blockIdx.x, t = threadIdx.x;   // 160 threads
    int j = t >> 4;
    __shared__ float so[F_];
    const float* pj = g_p2 + b*J_*K_ + j*K_;
    const float* wt = g_wt + t*K_;
    float acc = 0.f;
#pragma unroll 16
    for (int k = 0; k < K_; k++) acc += pj[k] * wt[k];
    so[t] = acc;
    __syncthreads();
    float s2 = 0.f;
#pragma unroll
    for (int d2 = 0; d2 < D_; d2++) { float x = so[j*D_ + d2]; s2 += x*x; }
    out[b*F_ + t] = acc * s2 / ((1.f + s2) * sqrtf(s2 + 1e-7f));
}

extern "C" void kernel_launch(void* const* d_in, const int* in_sizes, int n_in,
                              void* d_out, int out_size) {
    const float* u = (const float*)d_in[0];
    const float* W = (const float*)d_in[1];
    float* out = (float*)d_out;

    k_sum<<<dim3(8, B_), 256>>>(u, W);   // slice sums + zero p + transpose W
    k_ov<<<B_, 256>>>(W, 0);             // o0 (c uniform), v1
    k_pass<<<256, 256>>>(u, 0);          // b1 -> softmax -> p1
    k_ov<<<B_, 256>>>(W, 1);             // o1, v2
    k_pass<<<256, 256>>>(u, 1);          // b2 -> softmax -> p2
    k_final<<<B_, F_>>>(W, out);         // o2 -> squash
}

// round 16
// speedup vs baseline: 1.8555x; 1.1481x over previous
#include <cuda_runtime.h>
#include <math.h>

#define B_  64
#define N_  2048
#define K_  128
#define J_  10
#define D_  16
#define F_  160   // J_*D_

typedef unsigned long long u64;

// scratch (device globals: no allocation allowed)
__device__ float g_s8[B_*8*K_];      // per-chunk partial sums of u
__device__ float g_wt[F_*K_];        // W transposed: wt[f*128 + k] = W[k*160 + f]
__device__ float g_p1[B_*J_*K_];     // p after routing iter 1
__device__ float g_p2[B_*J_*K_];     // p after routing iter 2

__device__ __forceinline__ u64 ffma2(u64 a, u64 b, u64 c) {
    u64 d; asm("fma.rn.f32x2 %0, %1, %2, %3;" : "=l"(d) : "l"(a), "l"(b), "l"(c));
    return d;
}
__device__ __forceinline__ u64 pack2(float x, float y) {
    u64 d; asm("mov.b64 %0, {%1, %2};" : "=l"(d) : "f"(x), "f"(y));
    return d;
}
__device__ __forceinline__ float2 unpack2(u64 v) {
    float2 r; asm("mov.b64 {%0, %1}, %2;" : "=f"(r.x), "=f"(r.y) : "l"(v));
    return r;
}

// launch 1: per-chunk partial sums of u (plain stores, no atomics) +
// spread housekeeping (zero p1/p2, transpose W) over the 512 blocks.
__global__ void k_sum(const float* __restrict__ u, const float* __restrict__ W) {
    int b = blockIdx.y, chunk = blockIdx.x;   // 8 chunks x 64 b
    int tid = threadIdx.x;
    int gid = b*8 + chunk;                    // 0..511
    // housekeeping: 320 p-zeros + 40 transposes per block, strided over 256 threads
    for (int i = tid; i < 360; i += 256) {
        if (i < 320) {
            int i0 = gid*320 + i;             // 512*320 = 163840 = 2*81920
            if (i0 < B_*J_*K_) g_p1[i0] = 0.f;
            else               g_p2[i0 - B_*J_*K_] = 0.f;
        } else {
            int w0 = gid*40 + (i - 320);      // 512*40 = 20480 = F_*K_
            int f = w0 >> 7, k = w0 & 127;
            g_wt[w0] = W[k*F_ + f];
        }
    }
    int k4 = tid & 31, rg = tid >> 5;
    const float4* up = (const float4*)(u + ((size_t)b*N_ + chunk*256 + rg*32)*K_);
    float4 acc = make_float4(0.f,0.f,0.f,0.f);
#pragma unroll 8
    for (int r = 0; r < 32; r++) {
        float4 t = up[r*32 + k4];
        acc.x += t.x; acc.y += t.y; acc.z += t.z; acc.w += t.w;
    }
    __shared__ float4 sred[8][32];
    sred[rg][k4] = acc;
    __syncthreads();
    if (rg == 0) {
#pragma unroll
        for (int i = 1; i < 8; i++) {
            float4 t = sred[i][k4];
            acc.x += t.x; acc.y += t.y; acc.z += t.z; acc.w += t.w;
        }
        ((float4*)(g_s8 + (b*8 + chunk)*K_))[k4] = acc;
    }
}

// fused pass: [prologue: compute v[b] in-block] -> dots -> softmax -> p accum.
// which==0: src = 0.1 * (sum of g_s8 slices); which==1: src = p1[b].
// o[f] = src . wt[f,:]  (thread-per-f, coalesced per-thread float4 stream)
// v[j,k] = sum_d o[j,d] * wt[j*16+d, k]  (consecutive k -> coalesced LDG per d)
// Main loop: 8 rows per warp-iteration, oct-relative loads (R12/R15-proven).
__global__ void __launch_bounds__(256, 2)
k_pass(const float* __restrict__ u, int which) {
    float* p = (which == 0) ? g_p1 : g_p2;
    int b = blockIdx.x >> 2;
    int seg = blockIdx.x & 3;              // 512 rows per block
    int tid = threadIdx.x;
    int warp = tid >> 5, lane = tid & 31;
    int oct = lane >> 2;

    __shared__ float sv[J_*K_];            // src, then v
    __shared__ float ps[J_*K_];
    __shared__ float so[F_];

    // ---- prologue step 1: stage src into sv; zero ps ----
    if (which == 0) {
        for (int i = tid; i < K_; i += 256) {
            float a = 0.f;
#pragma unroll
            for (int c = 0; c < 8; c++) a += g_s8[(b*8 + c)*K_ + i];
            sv[i] = 0.1f * a;              // fold the uniform-softmax 1/10
        }
    } else {
        const float* pb = g_p1 + b*J_*K_;
        for (int i = tid; i < J_*K_; i += 256) sv[i] = pb[i];
    }
    for (int i = tid; i < J_*K_; i += 256) ps[i] = 0.f;
    __syncthreads();

    // ---- prologue step 2: o[f] = src . wt[f,:] ----
    if (tid < F_) {
        const float4* wr = (const float4*)(g_wt + tid*K_);
        const float4* sp = (const float4*)(sv + ((which == 0) ? 0 : (tid >> 4)*K_));
        float a0 = 0.f, a1 = 0.f, a2 = 0.f, a3 = 0.f;
#pragma unroll
        for (int i = 0; i < 32; i += 4) {
            float4 w0 = wr[i],   s0 = sp[i];
            float4 w1 = wr[i+1], s1 = sp[i+1];
            float4 w2 = wr[i+2], s2 = sp[i+2];
            float4 w3 = wr[i+3], s3 = sp[i+3];
            a0 += w0.x*s0.x + w0.y*s0.y + w0.z*s0.z + w0.w*s0.w;
            a1 += w1.x*s1.x + w1.y*s1.y + w1.z*s1.z + w1.w*s1.w;
            a2 += w2.x*s2.x + w2.y*s2.y + w2.z*s2.z + w2.w*s2.w;
            a3 += w3.x*s3.x + w3.y*s3.y + w3.z*s3.z + w3.w*s3.w;
        }
        so[tid] = (a0 + a1) + (a2 + a3);
    }
    __syncthreads();

    // ---- prologue step 3: v[j,k] into sv (coalesced wt reads per d) ----
    for (int e = tid; e < J_*K_; e += 256) {
        int j = e >> 7, k = e & 127;
        const float* oj = so + j*D_;
        const float* wtc = g_wt + (j*D_)*K_ + k;
        float v = 0.f;
#pragma unroll
        for (int d = 0; d < D_; d++) v += oj[d] * wtc[d*K_];
        sv[e] = v;
    }
    __syncthreads();

    // ---- main loop ----
    u64 p20[J_], p21[J_];
#pragma unroll
    for (int j = 0; j < J_; j++) { p20[j] = 0ULL; p21[j] = 0ULL; }

    const float4* ub = (const float4*)(u + ((size_t)b*N_ + (size_t)seg*512)*K_);
    const float4* svl = ((const float4*)sv) + lane;   // sv[j*K_ + 4*lane]

#pragma unroll 1
    for (int it = 0; it < 8; it++) {
        int r0 = warp*64 + it*8;
        u64 a0[8], a1[8];
#pragma unroll
        for (int r = 0; r < 8; r++) {
            float4 t = ub[(r0 + (oct ^ r))*32 + lane];
            a0[r] = pack2(t.x, t.y);
            a1[r] = pack2(t.z, t.w);
        }

        float pd[J_];
#pragma unroll
        for (int j = 0; j < J_; j++) {
            float4 vv = svl[j*32];         // conflict-free LDS.128
            u64 v0 = pack2(vv.x, vv.y);
            u64 v1 = pack2(vv.z, vv.w);
            float s[8];
#pragma unroll
            for (int r = 0; r < 8; r++) {
                u64 acc = ffma2(a0[r], v0, ffma2(a1[r], v1, 0ULL));
                float2 f = unpack2(acc);
                s[r] = f.x + f.y;
            }
            s[0] += __shfl_xor_sync(0xffffffffu, s[4], 16);
            s[1] += __shfl_xor_sync(0xffffffffu, s[5], 16);
            s[2] += __shfl_xor_sync(0xffffffffu, s[6], 16);
            s[3] += __shfl_xor_sync(0xffffffffu, s[7], 16);
            s[0] += __shfl_xor_sync(0xffffffffu, s[2], 8);
            s[1] += __shfl_xor_sync(0xffffffffu, s[3], 8);
            s[0] += __shfl_xor_sync(0xffffffffu, s[1], 4);
            s[0] += __shfl_xor_sync(0xffffffffu, s[0], 2);
            s[0] += __shfl_xor_sync(0xffffffffu, s[0], 1);
            pd[j] = s[0];                   // full dot of row r0+oct
        }
        float m01 = fmaxf(pd[0], pd[1]), m23 = fmaxf(pd[2], pd[3]);
        float m45 = fmaxf(pd[4], pd[5]), m67 = fmaxf(pd[6], pd[7]);
        float m89 = fmaxf(pd[8], pd[9]);
        float mx = fmaxf(fmaxf(fmaxf(m01, m23), fmaxf(m45, m67)), m89);
        float Z = 0.f;
#pragma unroll
        for (int j = 0; j < J_; j++) { pd[j] = __expf(pd[j] - mx); Z += pd[j]; }
        float rZ = __fdividef(1.0f, Z);
#pragma unroll
        for (int j = 0; j < J_; j++) {
            float c0 = pd[j] * rZ;          // row r0+oct
            u64 cc = pack2(c0, c0);
            p20[j] = ffma2(cc, a0[0], p20[j]);
            p21[j] = ffma2(cc, a1[0], p21[j]);
#pragma unroll
            for (int r = 1; r < 8; r++) {
                float cr = __shfl_xor_sync(0xffffffffu, c0, r << 2);
                cc = pack2(cr, cr);
                p20[j] = ffma2(cc, a0[r], p20[j]);
                p21[j] = ffma2(cc, a1[r], p21[j]);
            }
        }
    }

    // aggregate the 8 warps via smem, then 1 coalesced gmem atomic pass
#pragma unroll
    for (int j = 0; j < J_; j++) {
        float2 a = unpack2(p20[j]);
        float2 c = unpack2(p21[j]);
        float* d = ps + j*K_ + lane*4;
        atomicAdd(d+0, a.x); atomicAdd(d+1, a.y);
        atomicAdd(d+2, c.x); atomicAdd(d+3, c.y);
    }
    __syncthreads();
    float* pb = p + b*J_*K_;
    for (int i = tid; i < J_*K_; i += 256)
        atomicAdd(pb + i, ps[i]);
}

// o2[b,j,d] = sum_k p2[b,j,k]*W[k,jd]; out = squash(o2) over d
__global__ void k_final(const float* __restrict__ W, float* __restrict__ out) {
    int b = blockIdx.x, t = threadIdx.x;   // 160 threads
    int j = t >> 4;
    __shared__ float so[F_];
    const float* pj = g_p2 + b*J_*K_ + j*K_;
    const float4* wt = (const float4*)(g_wt + t*K_);
    const float4* pj4 = (const float4*)pj;
    float a0 = 0.f, a1 = 0.f, a2 = 0.f, a3 = 0.f;
#pragma unroll
    for (int i = 0; i < 32; i += 4) {
        float4 w0 = wt[i],   s0 = pj4[i];
        float4 w1 = wt[i+1], s1 = pj4[i+1];
        float4 w2 = wt[i+2], s2 = pj4[i+2];
        float4 w3 = wt[i+3], s3 = pj4[i+3];
        a0 += w0.x*s0.x + w0.y*s0.y + w0.z*s0.z + w0.w*s0.w;
        a1 += w1.x*s1.x + w1.y*s1.y + w1.z*s1.z + w1.w*s1.w;
        a2 += w2.x*s2.x + w2.y*s2.y + w2.z*s2.z + w2.w*s2.w;
        a3 += w3.x*s3.x + w3.y*s3.y + w3.z*s3.z + w3.w*s3.w;
    }
    float acc = (a0 + a1) + (a2 + a3);
    so[t] = acc;
    __syncthreads();
    float s2 = 0.f;
#pragma unroll
    for (int d2 = 0; d2 < D_; d2++) { float x = so[j*D_ + d2]; s2 += x*x; }
    out[b*F_ + t] = acc * s2 / ((1.f + s2) * sqrtf(s2 + 1e-7f));
}

extern "C" void kernel_launch(void* const* d_in, const int* in_sizes, int n_in,
                              void* d_out, int out_size) {
    const float* u = (const float*)d_in[0];
    const float* W = (const float*)d_in[1];
    float* out = (float*)d_out;

    k_sum<<<dim3(8, B_), 256>>>(u, W);   // slice sums + zero p + transpose W
    k_pass<<<256, 256>>>(u, 0);          // [v1 prologue] pass 1 -> p1
    k_pass<<<256, 256>>>(u, 1);          // [v2 prologue] pass 2 -> p2
    k_final<<<B_, F_>>>(W, out);         // o2 -> squash
}

// round 17
// speedup vs baseline: 1.8562x; 1.0004x over previous
#include <cuda_runtime.h>
#include <math.h>

#define B_  64
#define N_  2048
#define K_  128
#define J_  10
#define D_  16
#define F_  160   // J_*D_

typedef unsigned long long u64;

// scratch (device globals: no allocation allowed)
__device__ float g_s8 [B_*8*K_];       // per-chunk partial sums of u
__device__ float g_wt [F_*K_];         // W transposed: wt[f*128+k] = W[k*160+f]
__device__ float g_ps0[256*J_*K_];     // pass-0 per-block p slices
__device__ float g_ps1[256*J_*K_];     // pass-1 per-block p slices
__device__ unsigned g_cnt[B_];         // election counters (mod-4, never reset)

__device__ __forceinline__ u64 ffma2(u64 a, u64 b, u64 c) {
    u64 d; asm("fma.rn.f32x2 %0, %1, %2, %3;" : "=l"(d) : "l"(a), "l"(b), "l"(c));
    return d;
}
__device__ __forceinline__ u64 pack2(float x, float y) {
    u64 d; asm("mov.b64 %0, {%1, %2};" : "=l"(d) : "f"(x), "f"(y));
    return d;
}
__device__ __forceinline__ float2 unpack2(u64 v) {
    float2 r; asm("mov.b64 {%0, %1}, %2;" : "=f"(r.x), "=f"(r.y) : "l"(v));
    return r;
}

// launch 1: per-chunk partial sums of u (plain stores) + W transpose spread
__global__ void k_sum(const float* __restrict__ u, const float* __restrict__ W) {
    int b = blockIdx.y, chunk = blockIdx.x;   // 8 chunks x 64 b
    int tid = threadIdx.x;
    int gid = b*8 + chunk;                    // 0..511
    for (int i = tid; i < 40; i += 256) {     // transpose: 512*40 = 20480 = F_*K_
        int w0 = gid*40 + i;
        int f = w0 >> 7, k = w0 & 127;
        g_wt[w0] = W[k*F_ + f];
    }
    int k4 = tid & 31, rg = tid >> 5;
    const float4* up = (const float4*)(u + ((size_t)b*N_ + chunk*256 + rg*32)*K_);
    float4 acc = make_float4(0.f,0.f,0.f,0.f);
#pragma unroll 8
    for (int r = 0; r < 32; r++) {
        float4 t = up[r*32 + k4];
        acc.x += t.x; acc.y += t.y; acc.z += t.z; acc.w += t.w;
    }
    __shared__ float4 sred[8][32];
    sred[rg][k4] = acc;
    __syncthreads();
    if (rg == 0) {
#pragma unroll
        for (int i = 1; i < 8; i++) {
            float4 t = sred[i][k4];
            acc.x += t.x; acc.y += t.y; acc.z += t.z; acc.w += t.w;
        }
        ((float4*)(g_s8 + (b*8 + chunk)*K_))[k4] = acc;
    }
}

// fused pass: [v prologue] -> dots -> softmax -> p accum -> slice store.
// which==0: src = 0.1*(sum of g_s8 slices); slice -> g_ps0. No tail.
// which==1: src = sum of 4 g_ps0 slices (p1); slice -> g_ps1; elected last
//           block per b sums slices, computes o2 (warp-per-f butterfly),
//           squash -> out.
__global__ void __launch_bounds__(256, 2)
k_pass(const float* __restrict__ u, float* __restrict__ out, int which) {
    int b = blockIdx.x >> 2;
    int seg = blockIdx.x & 3;              // 512 rows per block
    int tid = threadIdx.x;
    int warp = tid >> 5, lane = tid & 31;
    int oct = lane >> 2;

    __shared__ float sv[J_*K_];            // src, then v
    __shared__ float ps[J_*K_];
    __shared__ float so[F_];

    // ---- prologue step 1: stage src into sv; zero ps ----
    if (which == 0) {
        for (int i = tid; i < K_; i += 256) {
            float a = 0.f;
#pragma unroll
            for (int c = 0; c < 8; c++) a += g_s8[(b*8 + c)*K_ + i];
            sv[i] = 0.1f * a;              // fold the uniform-softmax 1/10
        }
    } else {
        for (int i = tid; i < J_*K_; i += 256) {
            float a = 0.f;
#pragma unroll
            for (int c = 0; c < 4; c++) a += g_ps0[(size_t)((b<<2) + c)*J_*K_ + i];
            sv[i] = a;                     // p1[b]
        }
    }
    for (int i = tid; i < J_*K_; i += 256) ps[i] = 0.f;
    __syncthreads();

    // ---- prologue step 2: o[f] = src . wt[f,:] ----
    if (tid < F_) {
        const float4* wr = (const float4*)(g_wt + tid*K_);
        const float4* sp = (const float4*)(sv + ((which == 0) ? 0 : (tid >> 4)*K_));
        float a0 = 0.f, a1 = 0.f, a2 = 0.f, a3 = 0.f;
#pragma unroll
        for (int i = 0; i < 32; i += 4) {
            float4 w0 = wr[i],   s0 = sp[i];
            float4 w1 = wr[i+1], s1 = sp[i+1];
            float4 w2 = wr[i+2], s2 = sp[i+2];
            float4 w3 = wr[i+3], s3 = sp[i+3];
            a0 += w0.x*s0.x + w0.y*s0.y + w0.z*s0.z + w0.w*s0.w;
            a1 += w1.x*s1.x + w1.y*s1.y + w1.z*s1.z + w1.w*s1.w;
            a2 += w2.x*s2.x + w2.y*s2.y + w2.z*s2.z + w2.w*s2.w;
            a3 += w3.x*s3.x + w3.y*s3.y + w3.z*s3.z + w3.w*s3.w;
        }
        so[tid] = (a0 + a1) + (a2 + a3);
    }
    __syncthreads();

    // ---- prologue step 3: v[j,k] into sv (coalesced wt reads per d) ----
    for (int e = tid; e < J_*K_; e += 256) {
        int j = e >> 7, k = e & 127;
        const float* oj = so + j*D_;
        const float* wtc = g_wt + (j*D_)*K_ + k;
        float v = 0.f;
#pragma unroll
        for (int d = 0; d < D_; d++) v += oj[d] * wtc[d*K_];
        sv[e] = v;
    }
    __syncthreads();

    // ---- main loop (8 rows/warp-iter, oct-relative loads) ----
    u64 p20[J_], p21[J_];
#pragma unroll
    for (int j = 0; j < J_; j++) { p20[j] = 0ULL; p21[j] = 0ULL; }

    const float4* ub = (const float4*)(u + ((size_t)b*N_ + (size_t)seg*512)*K_);
    const float4* svl = ((const float4*)sv) + lane;   // sv[j*K_ + 4*lane]

#pragma unroll 1
    for (int it = 0; it < 8; it++) {
        int r0 = warp*64 + it*8;
        u64 a0[8], a1[8];
#pragma unroll
        for (int r = 0; r < 8; r++) {
            float4 t = ub[(r0 + (oct ^ r))*32 + lane];
            a0[r] = pack2(t.x, t.y);
            a1[r] = pack2(t.z, t.w);
        }

        float pd[J_];
#pragma unroll
        for (int j = 0; j < J_; j++) {
            float4 vv = svl[j*32];         // conflict-free LDS.128
            u64 v0 = pack2(vv.x, vv.y);
            u64 v1 = pack2(vv.z, vv.w);
            float s[8];
#pragma unroll
            for (int r = 0; r < 8; r++) {
                u64 acc = ffma2(a0[r], v0, ffma2(a1[r], v1, 0ULL));
                float2 f = unpack2(acc);
                s[r] = f.x + f.y;
            }
            s[0] += __shfl_xor_sync(0xffffffffu, s[4], 16);
            s[1] += __shfl_xor_sync(0xffffffffu, s[5], 16);
            s[2] += __shfl_xor_sync(0xffffffffu, s[6], 16);
            s[3] += __shfl_xor_sync(0xffffffffu, s[7], 16);
            s[0] += __shfl_xor_sync(0xffffffffu, s[2], 8);
            s[1] += __shfl_xor_sync(0xffffffffu, s[3], 8);
            s[0] += __shfl_xor_sync(0xffffffffu, s[1], 4);
            s[0] += __shfl_xor_sync(0xffffffffu, s[0], 2);
            s[0] += __shfl_xor_sync(0xffffffffu, s[0], 1);
            pd[j] = s[0];                   // full dot of row r0+oct
        }
        float m01 = fmaxf(pd[0], pd[1]), m23 = fmaxf(pd[2], pd[3]);
        float m45 = fmaxf(pd[4], pd[5]), m67 = fmaxf(pd[6], pd[7]);
        float m89 = fmaxf(pd[8], pd[9]);
        float mx = fmaxf(fmaxf(fmaxf(m01, m23), fmaxf(m45, m67)), m89);
        float Z = 0.f;
#pragma unroll
        for (int j = 0; j < J_; j++) { pd[j] = __expf(pd[j] - mx); Z += pd[j]; }
        float rZ = __fdividef(1.0f, Z);
#pragma unroll
        for (int j = 0; j < J_; j++) {
            float c0 = pd[j] * rZ;          // row r0+oct
            u64 cc = pack2(c0, c0);
            p20[j] = ffma2(cc, a0[0], p20[j]);
            p21[j] = ffma2(cc, a1[0], p21[j]);
#pragma unroll
            for (int r = 1; r < 8; r++) {
                float cr = __shfl_xor_sync(0xffffffffu, c0, r << 2);
                cc = pack2(cr, cr);
                p20[j] = ffma2(cc, a0[r], p20[j]);
                p21[j] = ffma2(cc, a1[r], p21[j]);
            }
        }
    }

    // aggregate the 8 warps via smem, then write this block's slice (plain STG)
#pragma unroll
    for (int j = 0; j < J_; j++) {
        float2 a = unpack2(p20[j]);
        float2 c = unpack2(p21[j]);
        float* d = ps + j*K_ + lane*4;
        atomicAdd(d+0, a.x); atomicAdd(d+1, a.y);
        atomicAdd(d+2, c.x); atomicAdd(d+3, c.y);
    }
    __syncthreads();
    {
        float* dst = (which == 0 ? g_ps0 : g_ps1) + (size_t)blockIdx.x*J_*K_;
        for (int i = tid; i < J_*K_; i += 256) dst[i] = ps[i];
    }
    if (which == 0) return;

    // ---- election: last of the 4 blocks for this b runs the final tail ----
    __threadfence();
    __syncthreads();
    __shared__ int lastf;
    if (tid == 0) lastf = ((atomicAdd(&g_cnt[b], 1u) & 3u) == 3u);
    __syncthreads();
    if (!lastf) return;
    __threadfence();

    // sum the 4 p2 slices (fixed order -> deterministic)
    for (int i = tid; i < J_*K_; i += 256) {
        float a = 0.f;
#pragma unroll
        for (int c = 0; c < 4; c++) a += g_ps1[(size_t)((b<<2) + c)*J_*K_ + i];
        ps[i] = a;
    }
    __syncthreads();

    // o2[f] via warp-per-f butterfly (latency-tolerant: 20 f per warp)
#pragma unroll
    for (int fi = 0; fi < 20; fi++) {
        int f = warp + fi*8;
        float4 w4 = ((const float4*)(g_wt + f*K_))[lane];
        float4 s4 = ((const float4*)(ps + (f >> 4)*K_))[lane];
        u64 acc = ffma2(pack2(w4.x, w4.y), pack2(s4.x, s4.y),
                  ffma2(pack2(w4.z, w4.w), pack2(s4.z, s4.w), 0ULL));
        float2 fr = unpack2(acc);
        float d = fr.x + fr.y;
#pragma unroll
        for (int m = 16; m >= 1; m >>= 1)
            d += __shfl_xor_sync(0xffffffffu, d, m);
        if (lane == 0) so[f] = d;
    }
    __syncthreads();

    // squash(o2) -> out
    if (tid < F_) {
        int j = tid >> 4;
        float s2 = 0.f;
#pragma unroll
        for (int d2 = 0; d2 < D_; d2++) { float x = so[j*D_ + d2]; s2 += x*x; }
        out[b*F_ + tid] = so[tid] * s2 / ((1.f + s2) * sqrtf(s2 + 1e-7f));
    }
}

extern "C" void kernel_launch(void* const* d_in, const int* in_sizes, int n_in,
                              void* d_out, int out_size) {
    const float* u = (const float*)d_in[0];
    const float* W = (const float*)d_in[1];
    float* out = (float*)d_out;

    k_sum<<<dim3(8, B_), 256>>>(u, W);       // slice sums + transpose W
    k_pass<<<256, 256>>>(u, out, 0);         // [v1 prologue] pass 1 -> p1 slices
    k_pass<<<256, 256>>>(u, out, 1);         // [v2 prologue] pass 2 + final tail
}